// round 6
// baseline (speedup 1.0000x reference)
#include <cuda_runtime.h>

// MoE conditional FFN: T=16, TOP_K=2, E=8, H=1024, I=2816, fp32.
// Expert-major grouping: each used expert's weights stream from HBM once.
// R4 (resubmitted after infra failure): both phases use the register
// front-batch recipe (load a large block of weight float4s into registers
// FIRST -> MLP_p1 ~ 11-16 -> HBM pipe fills), which R1's phase1 proved
// reaches ~5.1 TB/s. Occupancy is secondary to per-warp batched MLP.

#define NTOK   16
#define TOPK   2
#define NPAIR  (NTOK * TOPK)       // 32
#define HID    1024
#define INTER  2816
#define NEXP   8

__device__ float g_h[NPAIR * INTER];   // 360 KB scratch

__device__ __forceinline__ float dot4(float4 a, float4 b, float acc) {
    acc = fmaf(a.x, b.x, acc);
    acc = fmaf(a.y, b.y, acc);
    acc = fmaf(a.z, b.z, acc);
    return fmaf(a.w, b.w, acc);
}

// ---------------------------------------------------------------------------
// Phase 1 (identical to R1's proven version): gate & down GEMVs + SiLU-mul.
// grid = (INTER/32, NEXP), block = 256 (8 warps). Warp handles 4 rows; per row
// preloads 8+8 float4 weights into registers (front-batched, MLP_p1=16).
// ---------------------------------------------------------------------------
__global__ __launch_bounds__(256, 2)
void moe_phase1(const float* __restrict__ x,        // [T, H]
                const int*   __restrict__ eidx,     // [T, TOPK]
                const float* __restrict__ gate,     // [E, I, H]
                const float* __restrict__ down)     // [E, I, H]
{
    const int e = blockIdx.y;

    __shared__ int s_cnt;
    __shared__ int s_pair[NPAIR];
    if (threadIdx.x == 0) {
        int c = 0;
        #pragma unroll
        for (int i = 0; i < NPAIR; i++)
            if (eidx[i] == e) s_pair[c++] = i;
        s_cnt = c;
    }
    __syncthreads();
    const int cnt = s_cnt;
    if (cnt == 0) return;

    const int warp = threadIdx.x >> 5;
    const int lane = threadIdx.x & 31;
    const int row0 = blockIdx.x * 32 + warp * 4;

    const float4* gate4 = reinterpret_cast<const float4*>(gate + (size_t)e * INTER * HID);
    const float4* down4 = reinterpret_cast<const float4*>(down + (size_t)e * INTER * HID);

    for (int rr = 0; rr < 4; rr++) {
        const int row = row0 + rr;
        const float4* gr = gate4 + (size_t)row * (HID / 4);
        const float4* dr = down4 + (size_t)row * (HID / 4);

        float4 g4[8], d4[8];
        #pragma unroll
        for (int j = 0; j < 8; j++) {
            g4[j] = gr[lane + 32 * j];
            d4[j] = dr[lane + 32 * j];
        }

        for (int p = 0; p < cnt; p++) {
            const int pa = s_pair[p];
            const int t  = pa >> 1;
            const float4* xr = reinterpret_cast<const float4*>(x + (size_t)t * HID);

            float ag = 0.f, ad = 0.f;
            #pragma unroll
            for (int j = 0; j < 8; j++) {
                const float4 x4 = xr[lane + 32 * j];
                ag = dot4(g4[j], x4, ag);
                ad = dot4(d4[j], x4, ad);
            }
            #pragma unroll
            for (int off = 16; off; off >>= 1) {
                ag += __shfl_xor_sync(0xFFFFFFFFu, ag, off);
                ad += __shfl_xor_sync(0xFFFFFFFFu, ad, off);
            }
            if (lane == 0) {
                const float s = ag / (1.f + __expf(-ag));   // silu(gate)
                g_h[(size_t)pa * INTER + row] = s * ad;
            }
        }
    }
}

// ---------------------------------------------------------------------------
// Phase 2 (redesigned): out[pair,hh] = up[e,hh,:] . h[pair,:]
// grid = (HID/8, NEXP), block = 256 (8 warps). Warp = one row. Weight row is
// consumed in 2 halves of 11 float4/lane, each half PRELOADED into registers
// (front-batched, MLP_p1=11) before the 4-pair accumulation pass.
// ---------------------------------------------------------------------------
__global__ __launch_bounds__(256)
void moe_phase2(const int*   __restrict__ eidx,     // [T, TOPK]
                const float* __restrict__ up,       // [E, H, I]
                float*       __restrict__ out)      // [T, TOPK, H]
{
    const int e = blockIdx.y;

    __shared__ int s_cnt4;
    __shared__ int s_pair[NPAIR + 3];
    if (threadIdx.x == 0) {
        int c = 0;
        #pragma unroll
        for (int i = 0; i < NPAIR; i++)
            if (eidx[i] == e) s_pair[c++] = i;
        int c4 = (c + 3) & ~3;                 // pad to multiple of 4
        for (int i = c; i < c4; i++) s_pair[i] = s_pair[0];
        s_cnt4 = (c == 0) ? 0 : c4;
    }
    __syncthreads();
    const int cnt4 = s_cnt4;
    if (cnt4 == 0) return;

    const int warp = threadIdx.x >> 5;
    const int lane = threadIdx.x & 31;
    const int hh   = blockIdx.x * 8 + warp;

    const float4* ur = reinterpret_cast<const float4*>(up + (size_t)e * HID * INTER)
                       + (size_t)hh * (INTER / 4);  // 704 float4 per row

    for (int pb = 0; pb < cnt4; pb += 4) {
        const int pa0 = s_pair[pb + 0], pa1 = s_pair[pb + 1];
        const int pa2 = s_pair[pb + 2], pa3 = s_pair[pb + 3];
        const float4* h0 = reinterpret_cast<const float4*>(g_h + (size_t)pa0 * INTER);
        const float4* h1 = reinterpret_cast<const float4*>(g_h + (size_t)pa1 * INTER);
        const float4* h2 = reinterpret_cast<const float4*>(g_h + (size_t)pa2 * INTER);
        const float4* h3 = reinterpret_cast<const float4*>(g_h + (size_t)pa3 * INTER);

        float a0 = 0.f, a1 = 0.f, a2 = 0.f, a3 = 0.f;

        #pragma unroll
        for (int half = 0; half < 2; half++) {
            const int base = half * 11;

            float4 u[11];                      // front-batched weight loads
            #pragma unroll
            for (int j = 0; j < 11; j++)
                u[j] = ur[lane + 32 * (base + j)];

            #pragma unroll
            for (int j = 0; j < 11; j++) {
                const int k = lane + 32 * (base + j);
                a0 = dot4(u[j], h0[k], a0);
                a1 = dot4(u[j], h1[k], a1);
                a2 = dot4(u[j], h2[k], a2);
                a3 = dot4(u[j], h3[k], a3);
            }
        }

        #pragma unroll
        for (int off = 16; off; off >>= 1) {
            a0 += __shfl_xor_sync(0xFFFFFFFFu, a0, off);
            a1 += __shfl_xor_sync(0xFFFFFFFFu, a1, off);
            a2 += __shfl_xor_sync(0xFFFFFFFFu, a2, off);
            a3 += __shfl_xor_sync(0xFFFFFFFFu, a3, off);
        }
        if (lane == 0) {
            out[(size_t)pa0 * HID + hh] = a0;
            out[(size_t)pa1 * HID + hh] = a1;
            out[(size_t)pa2 * HID + hh] = a2;
            out[(size_t)pa3 * HID + hh] = a3;
        }
    }
}

// ---------------------------------------------------------------------------
extern "C" void kernel_launch(void* const* d_in, const int* in_sizes, int n_in,
                              void* d_out, int out_size)
{
    const float* x    = (const float*)d_in[0];
    const int*   eidx = (const int*)  d_in[1];
    const float* gate = (const float*)d_in[2];
    const float* up   = (const float*)d_in[3];
    const float* down = (const float*)d_in[4];
    float* out = (float*)d_out;

    dim3 g1(INTER / 32, NEXP);   // 88 x 8
    moe_phase1<<<g1, 256>>>(x, eidx, gate, down);

    dim3 g2(HID / 8, NEXP);      // 128 x 8
    moe_phase2<<<g2, 256>>>(eidx, up, out);
}

// round 7
// speedup vs baseline: 1.6310x; 1.6310x over previous
#include <cuda_runtime.h>

// MoE conditional FFN: T=16, TOP_K=2, E=8, H=1024, I=2816, fp32.
// Expert-major grouping: each used expert's weights stream from HBM once.
//
// R5: phase2 cloned onto the phase1 recipe that measured 6.5 TB/s in R6:
//   __launch_bounds__(256,2)  -> guaranteed 2 blocks = 16 warps/SM
//   FULL weight row front-batched into registers (22 float4, MLP_p1=22),
//   hoisted OUT of the pair loop; pair loop consumes L1/L2-resident h.
// R4's regs=130 -> 1 block/SM residency collapse is fixed by the (256,2) cap.

#define NTOK   16
#define TOPK   2
#define NPAIR  (NTOK * TOPK)       // 32
#define HID    1024
#define INTER  2816
#define NEXP   8

__device__ float g_h[NPAIR * INTER];   // 360 KB scratch

__device__ __forceinline__ float dot4(float4 a, float4 b, float acc) {
    acc = fmaf(a.x, b.x, acc);
    acc = fmaf(a.y, b.y, acc);
    acc = fmaf(a.z, b.z, acc);
    return fmaf(a.w, b.w, acc);
}

// ---------------------------------------------------------------------------
// Phase 1 (R1's proven version, 28.5us = 6.5 TB/s): gate & down GEMVs + SiLU.
// grid = (INTER/32, NEXP), block = 256 (8 warps). Warp handles 4 rows; per row
// preloads 8+8 float4 weights into registers (front-batched), pair loop reads
// x from L1.
// ---------------------------------------------------------------------------
__global__ __launch_bounds__(256, 2)
void moe_phase1(const float* __restrict__ x,        // [T, H]
                const int*   __restrict__ eidx,     // [T, TOPK]
                const float* __restrict__ gate,     // [E, I, H]
                const float* __restrict__ down)     // [E, I, H]
{
    const int e = blockIdx.y;

    __shared__ int s_cnt;
    __shared__ int s_pair[NPAIR];
    if (threadIdx.x == 0) {
        int c = 0;
        #pragma unroll
        for (int i = 0; i < NPAIR; i++)
            if (eidx[i] == e) s_pair[c++] = i;
        s_cnt = c;
    }
    __syncthreads();
    const int cnt = s_cnt;
    if (cnt == 0) return;

    const int warp = threadIdx.x >> 5;
    const int lane = threadIdx.x & 31;
    const int row0 = blockIdx.x * 32 + warp * 4;

    const float4* gate4 = reinterpret_cast<const float4*>(gate + (size_t)e * INTER * HID);
    const float4* down4 = reinterpret_cast<const float4*>(down + (size_t)e * INTER * HID);

    for (int rr = 0; rr < 4; rr++) {
        const int row = row0 + rr;
        const float4* gr = gate4 + (size_t)row * (HID / 4);
        const float4* dr = down4 + (size_t)row * (HID / 4);

        float4 g4[8], d4[8];
        #pragma unroll
        for (int j = 0; j < 8; j++) {
            g4[j] = gr[lane + 32 * j];
            d4[j] = dr[lane + 32 * j];
        }

        for (int p = 0; p < cnt; p++) {
            const int pa = s_pair[p];
            const int t  = pa >> 1;
            const float4* xr = reinterpret_cast<const float4*>(x + (size_t)t * HID);

            float ag = 0.f, ad = 0.f;
            #pragma unroll
            for (int j = 0; j < 8; j++) {
                const float4 x4 = xr[lane + 32 * j];
                ag = dot4(g4[j], x4, ag);
                ad = dot4(d4[j], x4, ad);
            }
            #pragma unroll
            for (int off = 16; off; off >>= 1) {
                ag += __shfl_xor_sync(0xFFFFFFFFu, ag, off);
                ad += __shfl_xor_sync(0xFFFFFFFFu, ad, off);
            }
            if (lane == 0) {
                const float s = ag / (1.f + __expf(-ag));   // silu(gate)
                g_h[(size_t)pa * INTER + row] = s * ad;
            }
        }
    }
}

// ---------------------------------------------------------------------------
// Phase 2 (phase1-recipe clone): out[pair,hh] = up[e,hh,:] . h[pair,:]
// grid = (HID/8, NEXP) = 1024 blocks, block = 256 (8 warps). Warp = one row.
// The ENTIRE weight row (22 float4/lane = 88 regs) is preloaded once, hoisted
// out of the pair loop. Pair loop: 22 L1/L2-hit h loads + 88 FMAs + reduce.
// ---------------------------------------------------------------------------
__global__ __launch_bounds__(256, 2)
void moe_phase2(const int*   __restrict__ eidx,     // [T, TOPK]
                const float* __restrict__ up,       // [E, H, I]
                float*       __restrict__ out)      // [T, TOPK, H]
{
    const int e = blockIdx.y;

    __shared__ int s_cnt;
    __shared__ int s_pair[NPAIR];
    if (threadIdx.x == 0) {
        int c = 0;
        #pragma unroll
        for (int i = 0; i < NPAIR; i++)
            if (eidx[i] == e) s_pair[c++] = i;
        s_cnt = c;
    }
    __syncthreads();
    const int cnt = s_cnt;
    if (cnt == 0) return;

    const int warp = threadIdx.x >> 5;
    const int lane = threadIdx.x & 31;
    const int hh   = blockIdx.x * 8 + warp;

    const float4* ur = reinterpret_cast<const float4*>(up + (size_t)e * HID * INTER)
                       + (size_t)hh * (INTER / 4);  // 704 float4 per row

    // Front-batch the full weight row: 22 independent LDG.128 up front.
    float4 u[22];
    #pragma unroll
    for (int j = 0; j < 22; j++)
        u[j] = ur[lane + 32 * j];

    for (int p = 0; p < cnt; p++) {
        const int pa = s_pair[p];
        const float4* hr = reinterpret_cast<const float4*>(g_h + (size_t)pa * INTER);

        float a0 = 0.f, a1 = 0.f;
        #pragma unroll
        for (int j = 0; j < 22; j += 2) {
            a0 = dot4(u[j],     hr[lane + 32 * j],       a0);
            a1 = dot4(u[j + 1], hr[lane + 32 * (j + 1)], a1);
        }
        float acc = a0 + a1;
        #pragma unroll
        for (int off = 16; off; off >>= 1)
            acc += __shfl_xor_sync(0xFFFFFFFFu, acc, off);
        if (lane == 0)
            out[(size_t)pa * HID + hh] = acc;
    }
}

// ---------------------------------------------------------------------------
extern "C" void kernel_launch(void* const* d_in, const int* in_sizes, int n_in,
                              void* d_out, int out_size)
{
    const float* x    = (const float*)d_in[0];
    const int*   eidx = (const int*)  d_in[1];
    const float* gate = (const float*)d_in[2];
    const float* up   = (const float*)d_in[3];
    const float* down = (const float*)d_in[4];
    float* out = (float*)d_out;

    dim3 g1(INTER / 32, NEXP);   // 88 x 8
    moe_phase1<<<g1, 256>>>(x, eidx, gate, down);

    dim3 g2(HID / 8, NEXP);      // 128 x 8
    moe_phase2<<<g2, 256>>>(eidx, up, out);
}